// round 1
// baseline (speedup 1.0000x reference)
#include <cuda_runtime.h>
#include <math_constants.h>

// Problem shape (fixed per reference): B=4, S=4096, D=1024
#define PB 4
#define PS 4096
#define PD 1024

// Scratch: Q, K, V (64 MB each), scores P (256 MB). Static device arrays
// (allocation-guard-safe per the harness rules).
__device__ float g_Q[(size_t)PB * PS * PD];
__device__ float g_K[(size_t)PB * PS * PD];
__device__ float g_V[(size_t)PB * PS * PD];
__device__ float g_P[(size_t)PB * PS * PS];

#define BM 128
#define BN 128
#define BK 16

// ---------------------------------------------------------------------------
// GEMM-NT: C[m,n] = scale * sum_k A[m,k] * B[n,k]  (+ bias[n] if bias != null)
// A: [M,K] row-major, B: [N,K] row-major. M,N multiples of 128, K multiple of 16.
// blockIdx.z selects batch via strides.
// ---------------------------------------------------------------------------
__global__ void __launch_bounds__(256)
gemm_nt_kernel(const float* __restrict__ A, const float* __restrict__ Bm,
               const float* __restrict__ bias, float* __restrict__ C,
               int M, int N, int K, float scale,
               size_t sA, size_t sB, size_t sC)
{
    A  += (size_t)blockIdx.z * sA;
    Bm += (size_t)blockIdx.z * sB;
    C  += (size_t)blockIdx.z * sC;

    __shared__ float As[BK][BM + 4];
    __shared__ float Bs[BK][BN + 4];

    const int tid = threadIdx.x;
    const int tx = tid & 15;      // 0..15 -> N direction
    const int ty = tid >> 4;      // 0..15 -> M direction
    const int row0 = blockIdx.y * BM;
    const int col0 = blockIdx.x * BN;

    float acc[8][8];
#pragma unroll
    for (int i = 0; i < 8; i++)
#pragma unroll
        for (int j = 0; j < 8; j++) acc[i][j] = 0.0f;

    for (int k0 = 0; k0 < K; k0 += BK) {
        // Load A tile (128x16) and B tile (128x16), both K-contiguous.
        // 512 float4 each; 2 per thread. Store transposed into smem.
#pragma unroll
        for (int i = 0; i < 2; i++) {
            int idx = tid * 2 + i;
            int r   = idx >> 2;          // 0..127
            int kk  = (idx & 3) * 4;     // 0,4,8,12
            float4 a = *reinterpret_cast<const float4*>(
                A + (size_t)(row0 + r) * K + (k0 + kk));
            As[kk + 0][r] = a.x; As[kk + 1][r] = a.y;
            As[kk + 2][r] = a.z; As[kk + 3][r] = a.w;
            float4 b = *reinterpret_cast<const float4*>(
                Bm + (size_t)(col0 + r) * K + (k0 + kk));
            Bs[kk + 0][r] = b.x; Bs[kk + 1][r] = b.y;
            Bs[kk + 2][r] = b.z; Bs[kk + 3][r] = b.w;
        }
        __syncthreads();

#pragma unroll
        for (int kk = 0; kk < BK; kk++) {
            float ra[8], rb[8];
            *reinterpret_cast<float4*>(&ra[0]) =
                *reinterpret_cast<const float4*>(&As[kk][ty * 8]);
            *reinterpret_cast<float4*>(&ra[4]) =
                *reinterpret_cast<const float4*>(&As[kk][ty * 8 + 4]);
            *reinterpret_cast<float4*>(&rb[0]) =
                *reinterpret_cast<const float4*>(&Bs[kk][tx * 8]);
            *reinterpret_cast<float4*>(&rb[4]) =
                *reinterpret_cast<const float4*>(&Bs[kk][tx * 8 + 4]);
#pragma unroll
            for (int i = 0; i < 8; i++)
#pragma unroll
                for (int j = 0; j < 8; j++)
                    acc[i][j] = fmaf(ra[i], rb[j], acc[i][j]);
        }
        __syncthreads();
    }

    float bv[8];
#pragma unroll
    for (int j = 0; j < 8; j++) bv[j] = 0.0f;
    if (bias) {
#pragma unroll
        for (int j = 0; j < 8; j++) bv[j] = bias[col0 + tx * 8 + j];
    }

#pragma unroll
    for (int i = 0; i < 8; i++) {
        float* cp = C + (size_t)(row0 + ty * 8 + i) * N + col0 + tx * 8;
        float4 o0, o1;
        o0.x = acc[i][0] * scale + bv[0];
        o0.y = acc[i][1] * scale + bv[1];
        o0.z = acc[i][2] * scale + bv[2];
        o0.w = acc[i][3] * scale + bv[3];
        o1.x = acc[i][4] * scale + bv[4];
        o1.y = acc[i][5] * scale + bv[5];
        o1.z = acc[i][6] * scale + bv[6];
        o1.w = acc[i][7] * scale + bv[7];
        reinterpret_cast<float4*>(cp)[0] = o0;
        reinterpret_cast<float4*>(cp)[1] = o1;
    }
}

// ---------------------------------------------------------------------------
// GEMM-NN: C[m,n] = sum_k A[m,k] * B[k,n]
// A: [M,K] row-major, B: [K,N] row-major.
// ---------------------------------------------------------------------------
__global__ void __launch_bounds__(256)
gemm_nn_kernel(const float* __restrict__ A, const float* __restrict__ Bm,
               float* __restrict__ C,
               int M, int N, int K,
               size_t sA, size_t sB, size_t sC)
{
    A  += (size_t)blockIdx.z * sA;
    Bm += (size_t)blockIdx.z * sB;
    C  += (size_t)blockIdx.z * sC;

    __shared__ float As[BK][BM + 4];
    __shared__ float Bs[BK][BN + 4];

    const int tid = threadIdx.x;
    const int tx = tid & 15;
    const int ty = tid >> 4;
    const int row0 = blockIdx.y * BM;
    const int col0 = blockIdx.x * BN;

    float acc[8][8];
#pragma unroll
    for (int i = 0; i < 8; i++)
#pragma unroll
        for (int j = 0; j < 8; j++) acc[i][j] = 0.0f;

    for (int k0 = 0; k0 < K; k0 += BK) {
#pragma unroll
        for (int i = 0; i < 2; i++) {
            int idx = tid * 2 + i;
            // A tile: 128 rows x 16 k, K-contiguous -> transpose into smem
            {
                int r  = idx >> 2;
                int kk = (idx & 3) * 4;
                float4 a = *reinterpret_cast<const float4*>(
                    A + (size_t)(row0 + r) * K + (k0 + kk));
                As[kk + 0][r] = a.x; As[kk + 1][r] = a.y;
                As[kk + 2][r] = a.z; As[kk + 3][r] = a.w;
            }
            // B tile: 16 k-rows x 128 n, N-contiguous -> direct vector store
            {
                int r = idx >> 5;            // 0..15
                int c = (idx & 31) * 4;      // 0..124
                float4 b = *reinterpret_cast<const float4*>(
                    Bm + (size_t)(k0 + r) * N + col0 + c);
                *reinterpret_cast<float4*>(&Bs[r][c]) = b;
            }
        }
        __syncthreads();

#pragma unroll
        for (int kk = 0; kk < BK; kk++) {
            float ra[8], rb[8];
            *reinterpret_cast<float4*>(&ra[0]) =
                *reinterpret_cast<const float4*>(&As[kk][ty * 8]);
            *reinterpret_cast<float4*>(&ra[4]) =
                *reinterpret_cast<const float4*>(&As[kk][ty * 8 + 4]);
            *reinterpret_cast<float4*>(&rb[0]) =
                *reinterpret_cast<const float4*>(&Bs[kk][tx * 8]);
            *reinterpret_cast<float4*>(&rb[4]) =
                *reinterpret_cast<const float4*>(&Bs[kk][tx * 8 + 4]);
#pragma unroll
            for (int i = 0; i < 8; i++)
#pragma unroll
                for (int j = 0; j < 8; j++)
                    acc[i][j] = fmaf(ra[i], rb[j], acc[i][j]);
        }
        __syncthreads();
    }

#pragma unroll
    for (int i = 0; i < 8; i++) {
        float* cp = C + (size_t)(row0 + ty * 8 + i) * N + col0 + tx * 8;
        float4 o0, o1;
        o0.x = acc[i][0]; o0.y = acc[i][1]; o0.z = acc[i][2]; o0.w = acc[i][3];
        o1.x = acc[i][4]; o1.y = acc[i][5]; o1.z = acc[i][6]; o1.w = acc[i][7];
        reinterpret_cast<float4*>(cp)[0] = o0;
        reinterpret_cast<float4*>(cp)[1] = o1;
    }
}

// ---------------------------------------------------------------------------
// Row softmax, in place. One block per row of 4096. Values held in registers:
// one global read + one global write per element.
// ---------------------------------------------------------------------------
__global__ void __launch_bounds__(256)
softmax_kernel(float* __restrict__ P, int N)
{
    float* row = P + (size_t)blockIdx.x * N;
    const int tid  = threadIdx.x;
    const int lane = tid & 31;
    const int warp = tid >> 5;

    float v[16];
    float m = -CUDART_INF_F;
#pragma unroll
    for (int i = 0; i < 16; i++) {
        v[i] = row[tid + i * 256];
        m = fmaxf(m, v[i]);
    }

    __shared__ float red[8];
#pragma unroll
    for (int o = 16; o > 0; o >>= 1)
        m = fmaxf(m, __shfl_xor_sync(0xffffffffu, m, o));
    if (lane == 0) red[warp] = m;
    __syncthreads();
    float bm = red[0];
#pragma unroll
    for (int w = 1; w < 8; w++) bm = fmaxf(bm, red[w]);
    __syncthreads();   // everyone done reading red before reuse

    float s = 0.0f;
#pragma unroll
    for (int i = 0; i < 16; i++) {
        v[i] = __expf(v[i] - bm);
        s += v[i];
    }
#pragma unroll
    for (int o = 16; o > 0; o >>= 1)
        s += __shfl_xor_sync(0xffffffffu, s, o);
    if (lane == 0) red[warp] = s;
    __syncthreads();
    float bs = red[0];
#pragma unroll
    for (int w = 1; w < 8; w++) bs += red[w];

    float inv = 1.0f / bs;
#pragma unroll
    for (int i = 0; i < 16; i++)
        row[tid + i * 256] = v[i] * inv;
}

// ---------------------------------------------------------------------------
// Launcher
// ---------------------------------------------------------------------------
extern "C" void kernel_launch(void* const* d_in, const int* in_sizes, int n_in,
                              void* d_out, int out_size)
{
    (void)in_sizes; (void)n_in; (void)out_size;
    const float* x  = (const float*)d_in[0];
    const float* Wq = (const float*)d_in[1];
    const float* bq = (const float*)d_in[2];
    const float* Wk = (const float*)d_in[3];
    const float* bk = (const float*)d_in[4];
    const float* Wv = (const float*)d_in[5];
    const float* bv = (const float*)d_in[6];
    float* out = (float*)d_out;

    float *Q, *K, *V, *P;
    cudaGetSymbolAddress((void**)&Q, g_Q);
    cudaGetSymbolAddress((void**)&K, g_K);
    cudaGetSymbolAddress((void**)&V, g_V);
    cudaGetSymbolAddress((void**)&P, g_P);

    const int M = PB * PS;            // 16384
    const size_t strideQKV = (size_t)PS * PD;
    const size_t strideP   = (size_t)PS * PS;

    dim3 blk(256);

    // 1) QKV projections: [16384,1024] = x[16384,1024] @ W^T + b
    dim3 g1(PD / BN, M / BM, 1);
    gemm_nt_kernel<<<g1, blk>>>(x, Wq, bq, Q, M, PD, PD, 1.0f, 0, 0, 0);
    gemm_nt_kernel<<<g1, blk>>>(x, Wk, bk, K, M, PD, PD, 1.0f, 0, 0, 0);
    gemm_nt_kernel<<<g1, blk>>>(x, Wv, bv, V, M, PD, PD, 1.0f, 0, 0, 0);

    // 2) scores: P[b] = Q[b] @ K[b]^T / sqrt(D)
    dim3 g2(PS / BN, PS / BM, PB);
    gemm_nt_kernel<<<g2, blk>>>(Q, K, nullptr, P, PS, PS, PD, 0.03125f,
                                strideQKV, strideQKV, strideP);

    // 3) softmax over last dim, in place
    softmax_kernel<<<PB * PS, blk>>>(P, PS);

    // 4) out[b] = P[b] @ V[b]
    dim3 g3(PD / BN, PS / BM, PB);
    gemm_nn_kernel<<<g3, blk>>>(P, V, out, PS, PD, PS,
                                strideP, strideQKV, strideQKV);
}

// round 3
// speedup vs baseline: 2.4185x; 2.4185x over previous
#include <cuda_runtime.h>
#include <cuda_bf16.h>
#include <math_constants.h>
#include <cstdint>

// Problem shape (fixed): B=4, S=4096, D=1024
#define PB 4
#define PS 4096
#define PD 1024
#define MROWS (PB * PS)   // 16384

// ---------------------------------------------------------------------------
// Global scratch (allocation-guard-safe __device__ arrays)
// ---------------------------------------------------------------------------
__device__ __nv_bfloat16 g_xh[(size_t)MROWS * PD], g_xl[(size_t)MROWS * PD];
__device__ __nv_bfloat16 g_Wqh[PD * PD], g_Wql[PD * PD];
__device__ __nv_bfloat16 g_Wkh[PD * PD], g_Wkl[PD * PD];
__device__ __nv_bfloat16 g_Wvh[PD * PD], g_Wvl[PD * PD];
__device__ __nv_bfloat16 g_Qh[(size_t)MROWS * PD], g_Ql[(size_t)MROWS * PD];
__device__ __nv_bfloat16 g_Kh[(size_t)MROWS * PD], g_Kl[(size_t)MROWS * PD];
__device__ __nv_bfloat16 g_Vh[(size_t)MROWS * PD], g_Vl[(size_t)MROWS * PD];
__device__ float         g_P [(size_t)PB * PS * PS];
__device__ __nv_bfloat16 g_Ph[(size_t)PB * PS * PS], g_Pl[(size_t)PB * PS * PS];

// ---------------------------------------------------------------------------
// PTX helpers (baseline sm_80+ features only: compile-safe under compute_103)
// ---------------------------------------------------------------------------
__device__ __forceinline__ uint32_t smem_u32(const void* p) {
    uint32_t a;
    asm("{ .reg .u64 t; cvta.to.shared.u64 t, %1; cvt.u32.u64 %0, t; }"
        : "=r"(a) : "l"(p));
    return a;
}

__device__ __forceinline__ void cp16(uint32_t s, const void* g) {
    asm volatile("cp.async.cg.shared.global [%0], [%1], 16;" :: "r"(s), "l"(g));
}
__device__ __forceinline__ void cp_commit() {
    asm volatile("cp.async.commit_group;" ::: "memory");
}
__device__ __forceinline__ void cp_wait0() {
    asm volatile("cp.async.wait_group 0;" ::: "memory");
}

__device__ __forceinline__ void ldsm_x4(uint32_t a, uint32_t* r) {
    asm volatile("ldmatrix.sync.aligned.m8n8.x4.shared.b16 {%0,%1,%2,%3}, [%4];"
                 : "=r"(r[0]), "=r"(r[1]), "=r"(r[2]), "=r"(r[3]) : "r"(a));
}
__device__ __forceinline__ void ldsm_x4_t(uint32_t a, uint32_t* r) {
    asm volatile("ldmatrix.sync.aligned.m8n8.x4.trans.shared.b16 {%0,%1,%2,%3}, [%4];"
                 : "=r"(r[0]), "=r"(r[1]), "=r"(r[2]), "=r"(r[3]) : "r"(a));
}

__device__ __forceinline__ void mma_bf16(float* c, const uint32_t* a,
                                         const uint32_t* b) {
    asm volatile(
        "mma.sync.aligned.m16n8k16.row.col.f32.bf16.bf16.f32 "
        "{%0,%1,%2,%3},{%4,%5,%6,%7},{%8,%9},{%0,%1,%2,%3};"
        : "+f"(c[0]), "+f"(c[1]), "+f"(c[2]), "+f"(c[3])
        : "r"(a[0]), "r"(a[1]), "r"(a[2]), "r"(a[3]), "r"(b[0]), "r"(b[1]));
}

__device__ __forceinline__ void split1(float v, __nv_bfloat16& h, __nv_bfloat16& l) {
    h = __float2bfloat16(v);
    l = __float2bfloat16(v - __bfloat162float(h));
}

// ---------------------------------------------------------------------------
// Tiling: block 128x128, BK=32, 8 warps each 32(M) x 64(N).
// SMEM per stage: A hi/lo 128 rows x 80B pad = 2*10240; B (NT) same = 2*10240,
// or B (BT) 32 k-rows x 272B pad = 2*8704. Stage stride 40960, 2 stages.
// 80B and 272B row strides are exactly conflict-free for ldmatrix phases.
// ---------------------------------------------------------------------------
#define STAGE_STRIDE 40960
#define SMEM_BYTES   (2 * STAGE_STRIDE)

// MODE 0: C = split bf16 (Ch/Cl) with +bias   (Q/K/V projections)
// MODE 2: C = fp32 * scale                     (scores, PV output)
// BT: B stored [K,N] (row-major V / NN GEMM) -> ldmatrix.trans path.
template<int MODE, bool BT>
__global__ void __launch_bounds__(256, 1)
gemm_mma(const __nv_bfloat16* __restrict__ Ah, const __nv_bfloat16* __restrict__ Al,
         const __nv_bfloat16* __restrict__ Bh, const __nv_bfloat16* __restrict__ Bl,
         const float* __restrict__ bias,
         float* __restrict__ Cf,
         __nv_bfloat16* __restrict__ Ch, __nv_bfloat16* __restrict__ Cl,
         int K, int ldb, int ldc, float scale,
         size_t sA, size_t sB, size_t sC)
{
    extern __shared__ char smem[];
    const uint32_t sb0 = smem_u32(smem);
    const int tid  = threadIdx.x;
    const int lane = tid & 31;
    const int wid  = tid >> 5;
    const int warp_m = wid & 3;        // 4 warps along M (32 rows each)
    const int warp_n = wid >> 2;       // 2 warps along N (64 cols each)

    Ah += (size_t)blockIdx.z * sA;  Al += (size_t)blockIdx.z * sA;
    Bh += (size_t)blockIdx.z * sB;  Bl += (size_t)blockIdx.z * sB;

    const int row0 = blockIdx.y * 128;
    const int col0 = blockIdx.x * 128;

    float acc[2][8][4];
#pragma unroll
    for (int i = 0; i < 2; i++)
#pragma unroll
        for (int n = 0; n < 8; n++)
#pragma unroll
            for (int j = 0; j < 4; j++) acc[i][n][j] = 0.0f;

    const int nk = K >> 5;   // BK = 32

    // ---------------- stage loader ----------------
    auto load_stage = [&](int stage, int k0) {
        const uint32_t sb = sb0 + stage * STAGE_STRIDE;
        // A: 1024 x 16B chunks (hi 512 + lo 512), 4 per thread
#pragma unroll
        for (int it = 0; it < 4; it++) {
            int idx = tid + (it << 8);
            int hl  = idx >> 9;
            int e   = idx & 511;
            int r   = e >> 2;            // 0..127
            int c4  = e & 3;             // 16B chunk within 64B row
            const __nv_bfloat16* src = hl ? Al : Ah;
            cp16(sb + hl * 10240 + r * 80 + c4 * 16,
                 src + (size_t)(row0 + r) * K + k0 + c4 * 8);
        }
        if (!BT) {
            // B: [N,K] tile 128 x 32, same layout as A
#pragma unroll
            for (int it = 0; it < 4; it++) {
                int idx = tid + (it << 8);
                int hl  = idx >> 9;
                int e   = idx & 511;
                int r   = e >> 2;
                int c4  = e & 3;
                const __nv_bfloat16* src = hl ? Bl : Bh;
                cp16(sb + 20480 + hl * 10240 + r * 80 + c4 * 16,
                     src + (size_t)(col0 + r) * ldb + k0 + c4 * 8);
            }
        } else {
            // B: [K,N] tile 32 x 128, rows padded to 272B
#pragma unroll
            for (int it = 0; it < 4; it++) {
                int idx = tid + (it << 8);
                int hl  = idx >> 9;
                int e   = idx & 511;
                int r   = e >> 4;            // 0..31 (k)
                int c16 = e & 15;            // 16B chunk within 256B row
                const __nv_bfloat16* src = hl ? Bl : Bh;
                cp16(sb + 20480 + hl * 8704 + r * 272 + c16 * 16,
                     src + (size_t)(k0 + r) * ldb + col0 + c16 * 8);
            }
        }
        cp_commit();
    };

    // ---------------- mainloop ----------------
    load_stage(0, 0);
    cp_wait0();
    __syncthreads();

    for (int i = 0; i < nk; i++) {
        if (i + 1 < nk) load_stage((i + 1) & 1, (i + 1) << 5);

        const uint32_t sA0 = sb0 + (i & 1) * STAGE_STRIDE;
        const uint32_t sB0 = sA0 + 20480;

#pragma unroll
        for (int kk = 0; kk < 2; kk++) {
            const int k16 = kk << 4;

            // A fragments (hi, lo) for this warp's two m16 tiles
            uint32_t ah[2][4], al[2][4];
#pragma unroll
            for (int mi = 0; mi < 2; mi++) {
                int m = warp_m * 32 + mi * 16 + (lane & 15);
                int k = k16 + ((lane & 16) ? 8 : 0);
                ldsm_x4(sA0 +         m * 80 + k * 2, ah[mi]);
                ldsm_x4(sA0 + 10240 + m * 80 + k * 2, al[mi]);
            }

            // B fragments: 8 n8-tiles via 4 x4-ldmatrix (hi and lo)
            uint32_t bh[8][2], bl[8][2];
#pragma unroll
            for (int nt = 0; nt < 4; nt++) {
                uint32_t r4[4];
                if (!BT) {
                    int n = warp_n * 64 + nt * 16 + ((lane & 16) ? 8 : 0) + (lane & 7);
                    int k = k16 + (lane & 8);
                    ldsm_x4(sB0 +         n * 80 + k * 2, r4);
                    bh[2 * nt][0] = r4[0]; bh[2 * nt][1] = r4[1];
                    bh[2 * nt + 1][0] = r4[2]; bh[2 * nt + 1][1] = r4[3];
                    ldsm_x4(sB0 + 10240 + n * 80 + k * 2, r4);
                    bl[2 * nt][0] = r4[0]; bl[2 * nt][1] = r4[1];
                    bl[2 * nt + 1][0] = r4[2]; bl[2 * nt + 1][1] = r4[3];
                } else {
                    int k = k16 + (lane & 15);
                    int n = warp_n * 64 + nt * 16 + ((lane & 16) ? 8 : 0);
                    ldsm_x4_t(sB0 +        k * 272 + n * 2, r4);
                    bh[2 * nt][0] = r4[0]; bh[2 * nt][1] = r4[1];
                    bh[2 * nt + 1][0] = r4[2]; bh[2 * nt + 1][1] = r4[3];
                    ldsm_x4_t(sB0 + 8704 + k * 272 + n * 2, r4);
                    bl[2 * nt][0] = r4[0]; bl[2 * nt][1] = r4[1];
                    bl[2 * nt + 1][0] = r4[2]; bl[2 * nt + 1][1] = r4[3];
                }
            }

            // 3-term split MMA: hi*hi + hi*lo + lo*hi
#pragma unroll
            for (int mi = 0; mi < 2; mi++)
#pragma unroll
                for (int n = 0; n < 8; n++) {
                    mma_bf16(acc[mi][n], ah[mi], bh[n]);
                    mma_bf16(acc[mi][n], ah[mi], bl[n]);
                    mma_bf16(acc[mi][n], al[mi], bh[n]);
                }
        }

        if (i + 1 < nk) {
            cp_wait0();
            __syncthreads();
        }
    }

    // ---------------- epilogue ----------------
#pragma unroll
    for (int mi = 0; mi < 2; mi++) {
        const int rbase = row0 + warp_m * 32 + mi * 16 + (lane >> 2);
#pragma unroll
        for (int n = 0; n < 8; n++) {
            const int cb = col0 + warp_n * 64 + n * 8 + 2 * (lane & 3);
            if (MODE == 2) {
                float* base = Cf + (size_t)blockIdx.z * sC;
                float2 v0 = make_float2(acc[mi][n][0] * scale, acc[mi][n][1] * scale);
                float2 v1 = make_float2(acc[mi][n][2] * scale, acc[mi][n][3] * scale);
                *reinterpret_cast<float2*>(base + (size_t)rbase * ldc + cb) = v0;
                *reinterpret_cast<float2*>(base + (size_t)(rbase + 8) * ldc + cb) = v1;
            } else {
                float b0 = bias[cb], b1 = bias[cb + 1];
                __nv_bfloat16 h0, l0, h1, l1, h2, l2, h3, l3;
                split1(acc[mi][n][0] + b0, h0, l0);
                split1(acc[mi][n][1] + b1, h1, l1);
                split1(acc[mi][n][2] + b0, h2, l2);
                split1(acc[mi][n][3] + b1, h3, l3);
                __nv_bfloat162* dh0 = reinterpret_cast<__nv_bfloat162*>(
                    Ch + (size_t)rbase * ldc + cb);
                __nv_bfloat162* dl0 = reinterpret_cast<__nv_bfloat162*>(
                    Cl + (size_t)rbase * ldc + cb);
                __nv_bfloat162* dh1 = reinterpret_cast<__nv_bfloat162*>(
                    Ch + (size_t)(rbase + 8) * ldc + cb);
                __nv_bfloat162* dl1 = reinterpret_cast<__nv_bfloat162*>(
                    Cl + (size_t)(rbase + 8) * ldc + cb);
                *dh0 = __nv_bfloat162(h0, h1);
                *dl0 = __nv_bfloat162(l0, l1);
                *dh1 = __nv_bfloat162(h2, h3);
                *dl1 = __nv_bfloat162(l2, l3);
            }
        }
    }
}

// ---------------------------------------------------------------------------
// fp32 -> bf16 hi/lo split (elementwise)
// ---------------------------------------------------------------------------
__global__ void __launch_bounds__(256)
split_kernel(const float* __restrict__ in, __nv_bfloat16* __restrict__ hi,
             __nv_bfloat16* __restrict__ lo, size_t n4)
{
    size_t i = (size_t)blockIdx.x * blockDim.x + threadIdx.x;
    if (i >= n4) return;
    float4 v = reinterpret_cast<const float4*>(in)[i];
    float vv[4] = { v.x, v.y, v.z, v.w };
    uint32_t H[2], L[2];
#pragma unroll
    for (int j = 0; j < 2; j++) {
        __nv_bfloat16 h0, l0, h1, l1;
        split1(vv[2 * j],     h0, l0);
        split1(vv[2 * j + 1], h1, l1);
        H[j] = (uint32_t)__bfloat16_as_ushort(h0) |
               ((uint32_t)__bfloat16_as_ushort(h1) << 16);
        L[j] = (uint32_t)__bfloat16_as_ushort(l0) |
               ((uint32_t)__bfloat16_as_ushort(l1) << 16);
    }
    reinterpret_cast<uint2*>(hi)[i] = make_uint2(H[0], H[1]);
    reinterpret_cast<uint2*>(lo)[i] = make_uint2(L[0], L[1]);
}

// ---------------------------------------------------------------------------
// Row softmax: fp32 in -> split bf16 out. One block per row of 4096.
// ---------------------------------------------------------------------------
__global__ void __launch_bounds__(256)
softmax_kernel(const float* __restrict__ P, __nv_bfloat16* __restrict__ Ph,
               __nv_bfloat16* __restrict__ Pl)
{
    const float* row = P + (size_t)blockIdx.x * PS;
    __nv_bfloat16* oh = Ph + (size_t)blockIdx.x * PS;
    __nv_bfloat16* ol = Pl + (size_t)blockIdx.x * PS;
    const int tid  = threadIdx.x;
    const int lane = tid & 31;
    const int warp = tid >> 5;

    float v[16];
    float m = -CUDART_INF_F;
#pragma unroll
    for (int i = 0; i < 16; i++) {
        v[i] = row[tid + i * 256];
        m = fmaxf(m, v[i]);
    }
    __shared__ float red[8];
#pragma unroll
    for (int o = 16; o > 0; o >>= 1)
        m = fmaxf(m, __shfl_xor_sync(0xffffffffu, m, o));
    if (lane == 0) red[warp] = m;
    __syncthreads();
    float bm = red[0];
#pragma unroll
    for (int w = 1; w < 8; w++) bm = fmaxf(bm, red[w]);
    __syncthreads();

    float s = 0.0f;
#pragma unroll
    for (int i = 0; i < 16; i++) {
        v[i] = __expf(v[i] - bm);
        s += v[i];
    }
#pragma unroll
    for (int o = 16; o > 0; o >>= 1)
        s += __shfl_xor_sync(0xffffffffu, s, o);
    if (lane == 0) red[warp] = s;
    __syncthreads();
    float bs = red[0];
#pragma unroll
    for (int w = 1; w < 8; w++) bs += red[w];

    float inv = 1.0f / bs;
#pragma unroll
    for (int i = 0; i < 16; i++) {
        float o = v[i] * inv;
        __nv_bfloat16 h, l;
        split1(o, h, l);
        oh[tid + i * 256] = h;
        ol[tid + i * 256] = l;
    }
}

// ---------------------------------------------------------------------------
// Launcher
// ---------------------------------------------------------------------------
extern "C" void kernel_launch(void* const* d_in, const int* in_sizes, int n_in,
                              void* d_out, int out_size)
{
    (void)in_sizes; (void)n_in; (void)out_size;
    const float* x  = (const float*)d_in[0];
    const float* Wq = (const float*)d_in[1];
    const float* bq = (const float*)d_in[2];
    const float* Wk = (const float*)d_in[3];
    const float* bk = (const float*)d_in[4];
    const float* Wv = (const float*)d_in[5];
    const float* bv = (const float*)d_in[6];
    float* out = (float*)d_out;

    __nv_bfloat16 *xh, *xl, *Wqh, *Wql, *Wkh, *Wkl, *Wvh, *Wvl;
    __nv_bfloat16 *Qh, *Ql, *Kh, *Kl, *Vh, *Vl, *Ph, *Pl;
    float* P;
    cudaGetSymbolAddress((void**)&xh,  g_xh);
    cudaGetSymbolAddress((void**)&xl,  g_xl);
    cudaGetSymbolAddress((void**)&Wqh, g_Wqh);
    cudaGetSymbolAddress((void**)&Wql, g_Wql);
    cudaGetSymbolAddress((void**)&Wkh, g_Wkh);
    cudaGetSymbolAddress((void**)&Wkl, g_Wkl);
    cudaGetSymbolAddress((void**)&Wvh, g_Wvh);
    cudaGetSymbolAddress((void**)&Wvl, g_Wvl);
    cudaGetSymbolAddress((void**)&Qh,  g_Qh);
    cudaGetSymbolAddress((void**)&Ql,  g_Ql);
    cudaGetSymbolAddress((void**)&Kh,  g_Kh);
    cudaGetSymbolAddress((void**)&Kl,  g_Kl);
    cudaGetSymbolAddress((void**)&Vh,  g_Vh);
    cudaGetSymbolAddress((void**)&Vl,  g_Vl);
    cudaGetSymbolAddress((void**)&P,   g_P);
    cudaGetSymbolAddress((void**)&Ph,  g_Ph);
    cudaGetSymbolAddress((void**)&Pl,  g_Pl);

    cudaFuncSetAttribute((const void*)gemm_mma<0, false>,
                         cudaFuncAttributeMaxDynamicSharedMemorySize, SMEM_BYTES);
    cudaFuncSetAttribute((const void*)gemm_mma<2, false>,
                         cudaFuncAttributeMaxDynamicSharedMemorySize, SMEM_BYTES);
    cudaFuncSetAttribute((const void*)gemm_mma<2, true>,
                         cudaFuncAttributeMaxDynamicSharedMemorySize, SMEM_BYTES);

    const size_t SD = (size_t)PS * PD;   // 4M elems per batch
    const size_t SS = (size_t)PS * PS;   // 16M elems per batch

    // 1) splits
    split_kernel<<<16384, 256>>>(x,  xh,  xl,  (size_t)MROWS * PD / 4);
    split_kernel<<<1024,  256>>>(Wq, Wqh, Wql, (size_t)PD * PD / 4);
    split_kernel<<<1024,  256>>>(Wk, Wkh, Wkl, (size_t)PD * PD / 4);
    split_kernel<<<1024,  256>>>(Wv, Wvh, Wvl, (size_t)PD * PD / 4);

    // 2) projections: [16384,1024] = x @ W^T + b  -> split bf16
    dim3 gp(PD / 128, MROWS / 128, 1);
    gemm_mma<0, false><<<gp, 256, SMEM_BYTES>>>(
        xh, xl, Wqh, Wql, bq, nullptr, Qh, Ql, PD, PD, PD, 1.0f, 0, 0, 0);
    gemm_mma<0, false><<<gp, 256, SMEM_BYTES>>>(
        xh, xl, Wkh, Wkl, bk, nullptr, Kh, Kl, PD, PD, PD, 1.0f, 0, 0, 0);
    gemm_mma<0, false><<<gp, 256, SMEM_BYTES>>>(
        xh, xl, Wvh, Wvl, bv, nullptr, Vh, Vl, PD, PD, PD, 1.0f, 0, 0, 0);

    // 3) scores: P[b] = Q[b] @ K[b]^T / 32  (NT)
    dim3 gs(PS / 128, PS / 128, PB);
    gemm_mma<2, false><<<gs, 256, SMEM_BYTES>>>(
        Qh, Ql, Kh, Kl, nullptr, P, nullptr, nullptr, PD, PD, PS, 0.03125f,
        SD, SD, SS);

    // 4) softmax -> split bf16 P
    softmax_kernel<<<PB * PS, 256>>>(P, Ph, Pl);

    // 5) out[b] = P[b] @ V[b]  (NN: B is [K=S, N=D] row-major -> BT path)
    dim3 go(PD / 128, PS / 128, PB);
    gemm_mma<2, true><<<go, 256, SMEM_BYTES>>>(
        Ph, Pl, Vh, Vl, nullptr, out, nullptr, nullptr, PS, PD, PD, 1.0f,
        SS, SD, SD);
}